// round 6
// baseline (speedup 1.0000x reference)
#include <cuda_runtime.h>

// out[b,c] = H @ x[b,c] @ H^T for 65536 independent 32x32 fp32 matrices.
// One warp per matrix. f32x2 row-pair accumulators + DCT even/odd butterfly
// (H[i][31-k] = (-1)^i H[i][k]) fold each contraction to 16 k-steps.
// R5: all pack/unpack/splat MOVs removed from the mainloops:
//   - stage 1 consumes a precomputed interleaved (E,O) smem table, built
//     straight from gmem with scalar FADDs + vector stores (no movs).
//   - stage 2 consumes a pre-splatted Htd table (H duplicated into both
//     halves of each u64) instead of per-k splat movs.

#define S_DIM 32
#define TSTRIDE 36             // Tt rows: 32 + 4 pad floats
#define EOSTRIDE 68            // EO rows: 64 floats (32 (E,O) pairs) + 4 pad
#define WARPS_PER_BLOCK 8
#define MATS_PER_BLOCK WARPS_PER_BLOCK
#define NTHREADS (WARPS_PER_BLOCK * 32)
#define BUF_FLOATS 1152        // max(16*EOSTRIDE=1088, 32*TSTRIDE=1152)

typedef unsigned long long u64;

__device__ __forceinline__ void fma2(u64& d, u64 a, u64 b) {
    asm("fma.rn.f32x2 %0, %1, %2, %0;" : "+l"(d) : "l"(a), "l"(b));
}
__device__ __forceinline__ u64 fma2v(u64 a, u64 b, u64 c) {
    u64 d;
    asm("fma.rn.f32x2 %0, %1, %2, %3;" : "=l"(d) : "l"(a), "l"(b), "l"(c));
    return d;
}
__device__ __forceinline__ u64 add2(u64 a, u64 b) {
    u64 d;
    asm("add.rn.f32x2 %0, %1, %2;" : "=l"(d) : "l"(a), "l"(b));
    return d;
}
__device__ __forceinline__ float2 unpack2(u64 u) {
    float2 f;
    asm("mov.b64 {%0, %1}, %2;" : "=f"(f.x), "=f"(f.y) : "l"(u));
    return f;
}

#define NEG1_X2 0xBF800000BF800000ULL   // (-1.0f, -1.0f)

__global__ __launch_bounds__(NTHREADS, 3)
void dct2d_kernel(const float* __restrict__ x,
                  const float* __restrict__ H,
                  float* __restrict__ out,
                  int nMat)
{
    __shared__ __align__(16) float Ht16[16 * S_DIM];   // Ht16[k][i] = H[i][k], k<16
    __shared__ __align__(16) u64   Htd[16 * S_DIM];    // Htd[k][l]  = (H[l][k], H[l][k])
    __shared__ __align__(16) float buf[MATS_PER_BLOCK][BUF_FLOATS]; // EO, then Tt

    const int tid = threadIdx.x;

    // Build Ht16 and Htd once per block.
    #pragma unroll
    for (int e = tid; e < 16 * S_DIM; e += NTHREADS) {
        int k = e >> 5;          // 0..15
        int i = e & 31;          // 0..31
        float v = H[i * S_DIM + k];
        Ht16[k * S_DIM + i] = v;
        float2 d; d.x = v; d.y = v;
        reinterpret_cast<float2*>(Htd)[k * S_DIM + i] = d;
    }
    __syncthreads();

    const int warp = tid >> 5;
    const int lane = tid & 31;
    const int m = blockIdx.x * WARPS_PER_BLOCK + warp;
    if (m >= nMat) return;

    float* W = buf[warp];
    const float4* __restrict__ src =
        reinterpret_cast<const float4*>(x + (size_t)m * (S_DIM * S_DIM));

    // ---- build interleaved EO table straight from gmem ----
    // lane pair (2k, 2k+1) handles rows k and 31-k; each lane does 16 cols.
    {
        const int kk = lane >> 1;       // 0..15
        const int h  = lane & 1;        // column half
        const float4* rk = src + kk * 8 + h * 4;
        const float4* rr = src + (31 - kk) * 8 + h * 4;
        float* dstp = &W[kk * EOSTRIDE + h * 32];   // 32 floats per half
        #pragma unroll
        for (int q = 0; q < 4; q++) {
            float4 a = rk[q];
            float4 b = rr[q];
            float4 lo, hi;
            lo.x = a.x + b.x; lo.y = a.x - b.x;   // (E,O) col 0
            lo.z = a.y + b.y; lo.w = a.y - b.y;   // (E,O) col 1
            hi.x = a.z + b.z; hi.y = a.z - b.z;
            hi.z = a.w + b.w; hi.w = a.w - b.w;
            *reinterpret_cast<float4*>(dstp + q * 8)     = lo;
            *reinterpret_cast<float4*>(dstp + q * 8 + 4) = hi;
        }
    }
    __syncwarp();

    const int ti = lane >> 3;   // rows ti*8 .. ti*8+7
    const int tj = lane & 7;    // cols tj*4 .. tj*4+3

    // acc[p][c] packs rows (ti*8+2p [even], ti*8+2p+1 [odd]) at col tj*4+c
    u64 acc[4][4];
    #pragma unroll
    for (int p = 0; p < 4; p++)
        #pragma unroll
        for (int c = 0; c < 4; c++) acc[p][c] = 0ull;

    // ---- stage 1: pure LDS + fma2 (no movs, no in-loop butterfly) ----
    #pragma unroll 8
    for (int k = 0; k < 16; k++) {
        ulonglong2 aA = *reinterpret_cast<const ulonglong2*>(&Ht16[k * S_DIM + ti * 8]);
        ulonglong2 aB = *reinterpret_cast<const ulonglong2*>(&Ht16[k * S_DIM + ti * 8 + 4]);
        u64 a[4] = {aA.x, aA.y, aB.x, aB.y};

        ulonglong2 b0 = *reinterpret_cast<const ulonglong2*>(&W[k * EOSTRIDE + tj * 8]);
        ulonglong2 b1 = *reinterpret_cast<const ulonglong2*>(&W[k * EOSTRIDE + tj * 8 + 4]);
        u64 eo[4] = {b0.x, b0.y, b1.x, b1.y};

        #pragma unroll
        for (int p = 0; p < 4; p++)
            #pragma unroll
            for (int c = 0; c < 4; c++)
                fma2(acc[p][c], a[p], eo[c]);
    }
    __syncwarp();

    // ---- write T transposed: Tt[j][i] = T[i][j] (overwrites EO region) ----
    #pragma unroll
    for (int c = 0; c < 4; c++) {
        int row = tj * 4 + c;
        float2 f0 = unpack2(acc[0][c]), f1 = unpack2(acc[1][c]);
        float2 f2 = unpack2(acc[2][c]), f3 = unpack2(acc[3][c]);
        *reinterpret_cast<float4*>(&W[row * TSTRIDE + ti * 8]) =
            make_float4(f0.x, f0.y, f1.x, f1.y);
        *reinterpret_cast<float4*>(&W[row * TSTRIDE + ti * 8 + 4]) =
            make_float4(f2.x, f2.y, f3.x, f3.y);
    }
    __syncwarp();

    #pragma unroll
    for (int p = 0; p < 4; p++)
        #pragma unroll
        for (int c = 0; c < 4; c++) acc[p][c] = 0ull;

    // ---- stage 2: Out[i][l] = sum_{j<16} H[l][j] * (l even ? E2 : O2)[i][j]
    //      a-side butterfly on fma pipe (pair-aligned), b from pre-splatted Htd.
    #pragma unroll 8
    for (int k = 0; k < 16; k++) {
        ulonglong2 akA = *reinterpret_cast<const ulonglong2*>(&W[k * TSTRIDE + ti * 8]);
        ulonglong2 akB = *reinterpret_cast<const ulonglong2*>(&W[k * TSTRIDE + ti * 8 + 4]);
        ulonglong2 arA = *reinterpret_cast<const ulonglong2*>(&W[(31 - k) * TSTRIDE + ti * 8]);
        ulonglong2 arB = *reinterpret_cast<const ulonglong2*>(&W[(31 - k) * TSTRIDE + ti * 8 + 4]);
        u64 ak[4] = {akA.x, akA.y, akB.x, akB.y};
        u64 ar[4] = {arA.x, arA.y, arB.x, arB.y};

        u64 E[4], O[4];
        #pragma unroll
        for (int p = 0; p < 4; p++) {
            E[p] = add2(ak[p], ar[p]);
            O[p] = fma2v(ar[p], NEG1_X2, ak[p]);
        }

        ulonglong2 q0 = *reinterpret_cast<const ulonglong2*>(&Htd[k * S_DIM + tj * 4]);
        ulonglong2 q1 = *reinterpret_cast<const ulonglong2*>(&Htd[k * S_DIM + tj * 4 + 2]);
        u64 bb[4] = {q0.x, q0.y, q1.x, q1.y};

        #pragma unroll
        for (int p = 0; p < 4; p++) {
            fma2(acc[p][0], E[p], bb[0]);   // l even -> E
            fma2(acc[p][1], O[p], bb[1]);   // l odd  -> O
            fma2(acc[p][2], E[p], bb[2]);
            fma2(acc[p][3], O[p], bb[3]);
        }
    }

    // ---- store Out[32][32] (coalesced float4) ----
    float* __restrict__ dst = out + (size_t)m * (S_DIM * S_DIM);
    #pragma unroll
    for (int p = 0; p < 4; p++) {
        int i0 = ti * 8 + 2 * p;
        float2 c0 = unpack2(acc[p][0]), c1 = unpack2(acc[p][1]);
        float2 c2 = unpack2(acc[p][2]), c3 = unpack2(acc[p][3]);
        *reinterpret_cast<float4*>(&dst[i0 * S_DIM + tj * 4]) =
            make_float4(c0.x, c1.x, c2.x, c3.x);
        *reinterpret_cast<float4*>(&dst[(i0 + 1) * S_DIM + tj * 4]) =
            make_float4(c0.y, c1.y, c2.y, c3.y);
    }
}

extern "C" void kernel_launch(void* const* d_in, const int* in_sizes, int n_in,
                              void* d_out, int out_size)
{
    const float* x = (const float*)d_in[0];   // [B, C, 32, 32] fp32
    const float* H = (const float*)d_in[1];   // [32, 32] fp32
    float* out = (float*)d_out;

    int nMat = in_sizes[0] / (S_DIM * S_DIM); // 65536
    int blocks = (nMat + MATS_PER_BLOCK - 1) / MATS_PER_BLOCK;

    dct2d_kernel<<<blocks, NTHREADS>>>(x, H, out, nMat);
}

// round 7
// speedup vs baseline: 1.4648x; 1.4648x over previous
#include <cuda_runtime.h>

// out[b,c] = H @ x[b,c] @ H^T for 65536 independent 32x32 fp32 matrices.
// One warp per matrix. f32x2 row-pair accumulators + DCT even/odd butterfly
// (H[i][31-k] = (-1)^i H[i][k]): both contractions fold to 16 k-steps.
// R6 (fixing R5's layout mistakes):
//  - pass A loads X fully coalesced (row-octet mapping), butterflies in
//    registers, stores an interleaved (E,O) table with a bank swizzle
//    (group j at j*8+(j>>2)*4, row stride 68) -> stage-1 reads conflict-free.
//  - stage 1: 4 conflict-free LDS.128 + 16 fma2 per k. No movs.
//  - stage 2: pre-splatted Htd table with u64 swizzle (l+(l>>4)*2, stride 34)
//    -> 2 conflict-free LDS.128 replace 4 splat movs; a-side butterfly on
//    the fma pipe.

#define S_DIM 32
#define TSTRIDE 36             // Tt rows: 32 + 4 pad floats (conflict-free)
#define EOSTRIDE 68            // EO rows: swizzled, max offset 67
#define HDSTRIDE 34            // Htd rows in u64: swizzled, max offset 33
#define WARPS_PER_BLOCK 8
#define MATS_PER_BLOCK WARPS_PER_BLOCK
#define NTHREADS (WARPS_PER_BLOCK * 32)
#define BUF_FLOATS 1152        // max(16*EOSTRIDE=1088, 32*TSTRIDE=1152)

typedef unsigned long long u64;

__device__ __forceinline__ void fma2(u64& d, u64 a, u64 b) {
    asm("fma.rn.f32x2 %0, %1, %2, %0;" : "+l"(d) : "l"(a), "l"(b));
}
__device__ __forceinline__ u64 fma2v(u64 a, u64 b, u64 c) {
    u64 d;
    asm("fma.rn.f32x2 %0, %1, %2, %3;" : "=l"(d) : "l"(a), "l"(b), "l"(c));
    return d;
}
__device__ __forceinline__ u64 add2(u64 a, u64 b) {
    u64 d;
    asm("add.rn.f32x2 %0, %1, %2;" : "=l"(d) : "l"(a), "l"(b));
    return d;
}
__device__ __forceinline__ float2 unpack2(u64 u) {
    float2 f;
    asm("mov.b64 {%0, %1}, %2;" : "=f"(f.x), "=f"(f.y) : "l"(u));
    return f;
}

#define NEG1_X2 0xBF800000BF800000ULL   // (-1.0f, -1.0f)

__global__ __launch_bounds__(NTHREADS, 3)
void dct2d_kernel(const float* __restrict__ x,
                  const float* __restrict__ H,
                  float* __restrict__ out,
                  int nMat)
{
    __shared__ __align__(16) float Ht16[16 * S_DIM];      // Ht16[k][i] = H[i][k], k<16
    __shared__ __align__(16) u64   Htd[16 * HDSTRIDE];    // swizzled (H[l][k],H[l][k])
    __shared__ __align__(16) float buf[MATS_PER_BLOCK][BUF_FLOATS]; // EO, then Tt

    const int tid = threadIdx.x;

    // Build Ht16 and swizzled Htd once per block.
    #pragma unroll
    for (int e = tid; e < 16 * S_DIM; e += NTHREADS) {
        int k = e >> 5;          // 0..15
        int l = e & 31;          // 0..31
        float v = H[l * S_DIM + k];
        Ht16[k * S_DIM + l] = v;
        float2 d; d.x = v; d.y = v;
        // col l -> u64 offset l + (l>>4)*2 within the row (bank swizzle)
        reinterpret_cast<float2*>(Htd)[k * HDSTRIDE + l + ((l >> 4) << 1)] = d;
    }
    __syncthreads();

    const int warp = tid >> 5;
    const int lane = tid & 31;
    const int m = blockIdx.x * WARPS_PER_BLOCK + warp;
    if (m >= nMat) return;

    float* W = buf[warp];
    const float4* __restrict__ src =
        reinterpret_cast<const float4*>(x + (size_t)m * (S_DIM * S_DIM));

    // ---- pass A: coalesced gmem read + butterfly + swizzled EO store ----
    // lane l: octet o=l>>3 (row within quad), group g=l&7 (16B column group).
    {
        const int o = lane >> 3;
        const int g = lane & 7;
        const int eo_off = g * 8 + ((g >> 2) << 2);   // swizzled float offset
        #pragma unroll
        for (int q = 0; q < 4; q++) {
            int ra = 4 * q + o;            // 0..15
            int rb = 31 - ra;              // 31..16
            float4 a = src[ra * 8 + g];    // 128B fully-used per octet
            float4 b = src[rb * 8 + g];
            float* dstp = &W[ra * EOSTRIDE + eo_off];
            *reinterpret_cast<float4*>(dstp) =
                make_float4(a.x + b.x, a.x - b.x, a.y + b.y, a.y - b.y);
            *reinterpret_cast<float4*>(dstp + 4) =
                make_float4(a.z + b.z, a.z - b.z, a.w + b.w, a.w - b.w);
        }
    }
    __syncwarp();

    const int ti = lane >> 3;   // rows ti*8 .. ti*8+7
    const int tj = lane & 7;    // cols tj*4 .. tj*4+3
    const int eo_rd = tj * 8 + ((tj >> 2) << 2);     // same swizzle as writer

    // acc[p][c] packs rows (ti*8+2p [even], ti*8+2p+1 [odd]) at col tj*4+c
    u64 acc[4][4];
    #pragma unroll
    for (int p = 0; p < 4; p++)
        #pragma unroll
        for (int c = 0; c < 4; c++) acc[p][c] = 0ull;

    // ---- stage 1: T[i][j] = sum_{k<16} H[i][k] * (i even ? E : O)[k][j] ----
    // pure conflict-free LDS + fma2; butterflies already in the table.
    #pragma unroll 8
    for (int k = 0; k < 16; k++) {
        ulonglong2 aA = *reinterpret_cast<const ulonglong2*>(&Ht16[k * S_DIM + ti * 8]);
        ulonglong2 aB = *reinterpret_cast<const ulonglong2*>(&Ht16[k * S_DIM + ti * 8 + 4]);
        u64 a[4] = {aA.x, aA.y, aB.x, aB.y};

        ulonglong2 b0 = *reinterpret_cast<const ulonglong2*>(&W[k * EOSTRIDE + eo_rd]);
        ulonglong2 b1 = *reinterpret_cast<const ulonglong2*>(&W[k * EOSTRIDE + eo_rd + 4]);
        u64 eo[4] = {b0.x, b0.y, b1.x, b1.y};

        #pragma unroll
        for (int p = 0; p < 4; p++)
            #pragma unroll
            for (int c = 0; c < 4; c++)
                fma2(acc[p][c], a[p], eo[c]);
    }
    __syncwarp();

    // ---- write T transposed: Tt[j][i] = T[i][j] (overwrites EO region) ----
    #pragma unroll
    for (int c = 0; c < 4; c++) {
        int row = tj * 4 + c;
        float2 f0 = unpack2(acc[0][c]), f1 = unpack2(acc[1][c]);
        float2 f2 = unpack2(acc[2][c]), f3 = unpack2(acc[3][c]);
        *reinterpret_cast<float4*>(&W[row * TSTRIDE + ti * 8]) =
            make_float4(f0.x, f0.y, f1.x, f1.y);
        *reinterpret_cast<float4*>(&W[row * TSTRIDE + ti * 8 + 4]) =
            make_float4(f2.x, f2.y, f3.x, f3.y);
    }
    __syncwarp();

    #pragma unroll
    for (int p = 0; p < 4; p++)
        #pragma unroll
        for (int c = 0; c < 4; c++) acc[p][c] = 0ull;

    const int hd_rd = tj * 4 + ((tj >> 2) << 1);     // u64 offset, swizzled

    // ---- stage 2: Out[i][l] = sum_{j<16} H[l][j] * (l even ? E2 : O2)[i][j]
    // a-side butterfly on the fma pipe; b from swizzled pre-splat Htd.
    #pragma unroll 8
    for (int k = 0; k < 16; k++) {
        ulonglong2 akA = *reinterpret_cast<const ulonglong2*>(&W[k * TSTRIDE + ti * 8]);
        ulonglong2 akB = *reinterpret_cast<const ulonglong2*>(&W[k * TSTRIDE + ti * 8 + 4]);
        ulonglong2 arA = *reinterpret_cast<const ulonglong2*>(&W[(31 - k) * TSTRIDE + ti * 8]);
        ulonglong2 arB = *reinterpret_cast<const ulonglong2*>(&W[(31 - k) * TSTRIDE + ti * 8 + 4]);
        u64 ak[4] = {akA.x, akA.y, akB.x, akB.y};
        u64 ar[4] = {arA.x, arA.y, arB.x, arB.y};

        u64 E[4], O[4];
        #pragma unroll
        for (int p = 0; p < 4; p++) {
            E[p] = add2(ak[p], ar[p]);
            O[p] = fma2v(ar[p], NEG1_X2, ak[p]);
        }

        ulonglong2 q0 = *reinterpret_cast<const ulonglong2*>(&Htd[k * HDSTRIDE + hd_rd]);
        ulonglong2 q1 = *reinterpret_cast<const ulonglong2*>(&Htd[k * HDSTRIDE + hd_rd + 2]);
        u64 bb[4] = {q0.x, q0.y, q1.x, q1.y};

        #pragma unroll
        for (int p = 0; p < 4; p++) {
            fma2(acc[p][0], E[p], bb[0]);   // l even -> E
            fma2(acc[p][1], O[p], bb[1]);   // l odd  -> O
            fma2(acc[p][2], E[p], bb[2]);
            fma2(acc[p][3], O[p], bb[3]);
        }
    }

    // ---- store Out[32][32] (coalesced float4) ----
    float* __restrict__ dst = out + (size_t)m * (S_DIM * S_DIM);
    #pragma unroll
    for (int p = 0; p < 4; p++) {
        int i0 = ti * 8 + 2 * p;
        float2 c0 = unpack2(acc[p][0]), c1 = unpack2(acc[p][1]);
        float2 c2 = unpack2(acc[p][2]), c3 = unpack2(acc[p][3]);
        *reinterpret_cast<float4*>(&dst[i0 * S_DIM + tj * 4]) =
            make_float4(c0.x, c1.x, c2.x, c3.x);
        *reinterpret_cast<float4*>(&dst[(i0 + 1) * S_DIM + tj * 4]) =
            make_float4(c0.y, c1.y, c2.y, c3.y);
    }
}

extern "C" void kernel_launch(void* const* d_in, const int* in_sizes, int n_in,
                              void* d_out, int out_size)
{
    const float* x = (const float*)d_in[0];   // [B, C, 32, 32] fp32
    const float* H = (const float*)d_in[1];   // [32, 32] fp32
    float* out = (float*)d_out;

    int nMat = in_sizes[0] / (S_DIM * S_DIM); // 65536
    int blocks = (nMat + MATS_PER_BLOCK - 1) / MATS_PER_BLOCK;

    dct2d_kernel<<<blocks, NTHREADS>>>(x, H, out, nMat);
}